// round 4
// baseline (speedup 1.0000x reference)
#include <cuda_runtime.h>

#define NB 32
#define HH 640
#define WW 640
#define HW (HH * WW)
#define CH 8                    // batches per chunk (scratch = 2*26MB)
#define NCHUNK (NB / CH)
#define NCHW (NB * 2 * HW)

// Chunk-sized ping-pong scratch, interleaved float2 [CH,H,W,(x,y)].
__device__ float2 g_bufA[CH * HW];
__device__ float2 g_bufB[CH * HW];

// Bilinear sample (border clamp, align_corners=True) from interleaved field
// b[H*W] at normalized coords (tx,ty). EXACT round-3 arithmetic (passing).
__device__ __forceinline__ float2 samp(const float2* __restrict__ b,
                                       float tx, float ty) {
    float px = (tx + 1.0f) * (0.5f * (float)(WW - 1));
    float py = (ty + 1.0f) * (0.5f * (float)(HH - 1));
    px = fminf(fmaxf(px, 0.0f), (float)(WW - 1));
    py = fminf(fmaxf(py, 0.0f), (float)(HH - 1));
    float x0f = floorf(px);
    float y0f = floorf(py);
    int x0 = (int)x0f;
    int y0 = (int)y0f;
    int x1 = min(x0 + 1, WW - 1);
    int y1 = min(y0 + 1, HH - 1);
    float wx = px - x0f;
    float wy = py - y0f;
    float2 v00 = b[y0 * WW + x0];
    float2 v01 = b[y0 * WW + x1];
    float2 v10 = b[y1 * WW + x0];
    float2 v11 = b[y1 * WW + x1];
    float topx = v00.x * (1.0f - wx) + v01.x * wx;
    float topy = v00.y * (1.0f - wx) + v01.y * wx;
    float botx = v10.x * (1.0f - wx) + v11.x * wx;
    float boty = v10.y * (1.0f - wx) + v11.y * wx;
    return make_float2(topx * (1.0f - wy) + botx * wy,
                       topy * (1.0f - wy) + boty * wy);
}

// Planar sampler over v with scale S applied to each tap (round-3 exact).
__device__ __forceinline__ float2 sampP(const float* __restrict__ vx,
                                        const float* __restrict__ vy,
                                        float tx, float ty, float S) {
    float px = (tx + 1.0f) * (0.5f * (float)(WW - 1));
    float py = (ty + 1.0f) * (0.5f * (float)(HH - 1));
    px = fminf(fmaxf(px, 0.0f), (float)(WW - 1));
    py = fminf(fmaxf(py, 0.0f), (float)(HH - 1));
    float x0f = floorf(px);
    float y0f = floorf(py);
    int x0 = (int)x0f;
    int y0 = (int)y0f;
    int x1 = min(x0 + 1, WW - 1);
    int y1 = min(y0 + 1, HH - 1);
    float wx = px - x0f;
    float wy = py - y0f;
    float sx, sy;
    {
        float a00 = vx[y0 * WW + x0] * S, a01 = vx[y0 * WW + x1] * S;
        float a10 = vx[y1 * WW + x0] * S, a11 = vx[y1 * WW + x1] * S;
        float top = a00 * (1.0f - wx) + a01 * wx;
        float bot = a10 * (1.0f - wx) + a11 * wx;
        sx = top * (1.0f - wy) + bot * wy;
    }
    {
        float a00 = vy[y0 * WW + x0] * S, a01 = vy[y0 * WW + x1] * S;
        float a10 = vy[y1 * WW + x0] * S, a11 = vy[y1 * WW + x1] * S;
        float top = a00 * (1.0f - wx) + a01 * wx;
        float bot = a10 * (1.0f - wx) + a11 * wx;
        sy = top * (1.0f - wy) + bot * wy;
    }
    return make_float2(sx, sy);
}

// Thread mapping (all kernels): block = (160,2); blockIdx.x = row-pair,
// blockIdx.y = batch-in-chunk. Each thread: 4 consecutive pixels. No division.

// Iteration 0 for one chunk: disp0 = v*2^-32, one step, write interleaved.
__global__ __launch_bounds__(320, 4) void k_first(const float* __restrict__ v,
                                                  const float2* __restrict__ idg,
                                                  float2* __restrict__ dst) {
    int n = blockIdx.y;
    int y = blockIdx.x * 2 + threadIdx.y;
    int x = threadIdx.x * 4;
    int p = y * WW + x;
    const float* vx = v + (size_t)n * 2 * HW;
    const float* vy = vx + HW;
    const float S = 0x1p-32f;

    float4 g01 = *reinterpret_cast<const float4*>(idg + p);
    float4 g23 = *reinterpret_cast<const float4*>(idg + p + 2);

    float d0x = vx[p] * S,     d0y = vy[p] * S;
    float d1x = vx[p + 1] * S, d1y = vy[p + 1] * S;
    float d2x = vx[p + 2] * S, d2y = vy[p + 2] * S;
    float d3x = vx[p + 3] * S, d3y = vy[p + 3] * S;

    float2 s0 = sampP(vx, vy, g01.x + d0x, g01.y + d0y, S);
    float2 s1 = sampP(vx, vy, g01.z + d1x, g01.w + d1y, S);
    float2 s2 = sampP(vx, vy, g23.x + d2x, g23.y + d2y, S);
    float2 s3 = sampP(vx, vy, g23.z + d3x, g23.w + d3y, S);

    float2* o = dst + (size_t)n * HW + p;
    *reinterpret_cast<float4*>(o)     = make_float4(d0x + s0.x, d0y + s0.y,
                                                    d1x + s1.x, d1y + s1.y);
    *reinterpret_cast<float4*>(o + 2) = make_float4(d2x + s2.x, d2y + s2.y,
                                                    d3x + s3.x, d3y + s3.y);
}

// Middle iterations: interleaved -> interleaved, chunk ping-pong.
__global__ __launch_bounds__(320, 4) void k_step(const float2* __restrict__ src,
                                                 const float2* __restrict__ idg,
                                                 float2* __restrict__ dst) {
    int n = blockIdx.y;
    int y = blockIdx.x * 2 + threadIdx.y;
    int x = threadIdx.x * 4;
    int p = y * WW + x;
    const float2* b = src + (size_t)n * HW;

    float4 d01 = *reinterpret_cast<const float4*>(b + p);
    float4 d23 = *reinterpret_cast<const float4*>(b + p + 2);
    float4 g01 = *reinterpret_cast<const float4*>(idg + p);
    float4 g23 = *reinterpret_cast<const float4*>(idg + p + 2);

    float2 s0 = samp(b, g01.x + d01.x, g01.y + d01.y);
    float2 s1 = samp(b, g01.z + d01.z, g01.w + d01.w);
    float2 s2 = samp(b, g23.x + d23.x, g23.y + d23.y);
    float2 s3 = samp(b, g23.z + d23.z, g23.w + d23.w);

    float2* o = dst + (size_t)n * HW + p;
    *reinterpret_cast<float4*>(o)     = make_float4(d01.x + s0.x, d01.y + s0.y,
                                                    d01.z + s1.x, d01.w + s1.y);
    *reinterpret_cast<float4*>(o + 2) = make_float4(d23.x + s2.x, d23.y + s2.y,
                                                    d23.z + s3.x, d23.w + s3.y);
}

// Final iteration for one chunk: step + planar output write.
//   out[0:NCHW)      = transformation = idgrid + disp
//   out[NCHW:2*NCHW) = displacement
__global__ __launch_bounds__(320, 4) void k_last(const float2* __restrict__ src,
                                                 const float2* __restrict__ idg,
                                                 float* __restrict__ out,
                                                 int nglobBase) {
    int n = blockIdx.y;
    int y = blockIdx.x * 2 + threadIdx.y;
    int x = threadIdx.x * 4;
    int p = y * WW + x;
    const float2* b = src + (size_t)n * HW;

    float4 d01 = *reinterpret_cast<const float4*>(b + p);
    float4 d23 = *reinterpret_cast<const float4*>(b + p + 2);
    float4 g01 = *reinterpret_cast<const float4*>(idg + p);
    float4 g23 = *reinterpret_cast<const float4*>(idg + p + 2);

    float2 s0 = samp(b, g01.x + d01.x, g01.y + d01.y);
    float2 s1 = samp(b, g01.z + d01.z, g01.w + d01.w);
    float2 s2 = samp(b, g23.x + d23.x, g23.y + d23.y);
    float2 s3 = samp(b, g23.z + d23.z, g23.w + d23.w);

    float n0x = d01.x + s0.x, n0y = d01.y + s0.y;
    float n1x = d01.z + s1.x, n1y = d01.w + s1.y;
    float n2x = d23.x + s2.x, n2y = d23.y + s2.y;
    float n3x = d23.z + s3.x, n3y = d23.w + s3.y;

    size_t base = (size_t)(nglobBase + n) * 2 * HW + p;
    // transformation ch0 (x), ch1 (y)
    *reinterpret_cast<float4*>(out + base) =
        make_float4(g01.x + n0x, g01.z + n1x, g23.x + n2x, g23.z + n3x);
    *reinterpret_cast<float4*>(out + base + HW) =
        make_float4(g01.y + n0y, g01.w + n1y, g23.y + n2y, g23.w + n3y);
    // displacement ch0, ch1
    *reinterpret_cast<float4*>(out + NCHW + base) =
        make_float4(n0x, n1x, n2x, n3x);
    *reinterpret_cast<float4*>(out + NCHW + base + HW) =
        make_float4(n0y, n1y, n2y, n3y);
}

extern "C" void kernel_launch(void* const* d_in, const int* in_sizes, int n_in,
                              void* d_out, int out_size) {
    const float* v = (const float*)d_in[0];
    const float2* idg = (const float2*)d_in[1];  // [1,H,W,2] interleaved
    float* out = (float*)d_out;

    float2 *A, *B;
    cudaGetSymbolAddress((void**)&A, g_bufA);
    cudaGetSymbolAddress((void**)&B, g_bufB);

    dim3 threads(160, 2);                 // 320 threads: 2 rows x 160 (4 px each)
    dim3 blocks(HH / 2, CH);              // row-pairs x batches

    for (int c = 0; c < NCHUNK; ++c) {
        const float* vC = v + (size_t)c * CH * 2 * HW;

        // Iteration 0 (reads v planar, scale folded) -> A
        k_first<<<blocks, threads>>>(vC, idg, A);

        // Iterations 1..30 ping-pong within L2-resident scratch
        float2* src = A;
        float2* dst = B;
        for (int it = 1; it <= 30; ++it) {
            k_step<<<blocks, threads>>>(src, idg, dst);
            float2* t = src; src = dst; dst = t;
        }
        // After 30 steps result is back in A (src == A)

        // Iteration 31 fused with planar output write
        k_last<<<blocks, threads>>>(src, idg, out, c * CH);
    }
}

// round 5
// speedup vs baseline: 1.2550x; 1.2550x over previous
#include <cuda_runtime.h>

#define NB 32
#define HH 640
#define WW 640
#define HW (HH * WW)
#define CH 8                    // batches per chunk (scratch = 2*26MB)
#define NCHUNK (NB / CH)
#define NCHW (NB * 2 * HW)

#define BLK 256
#define PXB (BLK * 4)           // 1024 pixels per block
#define BLKS_PER_IMG (HW / PXB) // 400, exact

// Chunk-sized ping-pong scratch, interleaved float2 [CH,H,W,(x,y)].
__device__ float2 g_bufA[CH * HW];
__device__ float2 g_bufB[CH * HW];

// Bilinear sample (border clamp, align_corners=True) from interleaved field
// b[H*W] at normalized coords (tx,ty). EXACT arithmetic of passing rounds.
__device__ __forceinline__ float2 samp(const float2* __restrict__ b,
                                       float tx, float ty) {
    float px = (tx + 1.0f) * (0.5f * (float)(WW - 1));
    float py = (ty + 1.0f) * (0.5f * (float)(HH - 1));
    px = fminf(fmaxf(px, 0.0f), (float)(WW - 1));
    py = fminf(fmaxf(py, 0.0f), (float)(HH - 1));
    float x0f = floorf(px);
    float y0f = floorf(py);
    int x0 = (int)x0f;
    int y0 = (int)y0f;
    int x1 = min(x0 + 1, WW - 1);
    int y1 = min(y0 + 1, HH - 1);
    float wx = px - x0f;
    float wy = py - y0f;
    float2 v00 = b[y0 * WW + x0];
    float2 v01 = b[y0 * WW + x1];
    float2 v10 = b[y1 * WW + x0];
    float2 v11 = b[y1 * WW + x1];
    float topx = v00.x * (1.0f - wx) + v01.x * wx;
    float topy = v00.y * (1.0f - wx) + v01.y * wx;
    float botx = v10.x * (1.0f - wx) + v11.x * wx;
    float boty = v10.y * (1.0f - wx) + v11.y * wx;
    return make_float2(topx * (1.0f - wy) + botx * wy,
                       topy * (1.0f - wy) + boty * wy);
}

// Planar sampler over v with scale S applied to each tap (exact).
__device__ __forceinline__ float2 sampP(const float* __restrict__ vx,
                                        const float* __restrict__ vy,
                                        float tx, float ty, float S) {
    float px = (tx + 1.0f) * (0.5f * (float)(WW - 1));
    float py = (ty + 1.0f) * (0.5f * (float)(HH - 1));
    px = fminf(fmaxf(px, 0.0f), (float)(WW - 1));
    py = fminf(fmaxf(py, 0.0f), (float)(HH - 1));
    float x0f = floorf(px);
    float y0f = floorf(py);
    int x0 = (int)x0f;
    int y0 = (int)y0f;
    int x1 = min(x0 + 1, WW - 1);
    int y1 = min(y0 + 1, HH - 1);
    float wx = px - x0f;
    float wy = py - y0f;
    float sx, sy;
    {
        float a00 = vx[y0 * WW + x0] * S, a01 = vx[y0 * WW + x1] * S;
        float a10 = vx[y1 * WW + x0] * S, a11 = vx[y1 * WW + x1] * S;
        float top = a00 * (1.0f - wx) + a01 * wx;
        float bot = a10 * (1.0f - wx) + a11 * wx;
        sx = top * (1.0f - wy) + bot * wy;
    }
    {
        float a00 = vy[y0 * WW + x0] * S, a01 = vy[y0 * WW + x1] * S;
        float a10 = vy[y1 * WW + x0] * S, a11 = vy[y1 * WW + x1] * S;
        float top = a00 * (1.0f - wx) + a01 * wx;
        float bot = a10 * (1.0f - wx) + a11 * wx;
        sy = top * (1.0f - wy) + bot * wy;
    }
    return make_float2(sx, sy);
}

// Mapping (all kernels): blockIdx.y = batch-in-chunk, blockIdx.x covers 1024
// consecutive pixels; thread t handles pixels base+t+{0,256,512,768}.
// Every load/store is lane-contiguous (fully coalesced), ILP = 4 samples.

// Iteration 0 for one chunk: disp0 = v*2^-32, one step, write interleaved.
__global__ __launch_bounds__(BLK, 4) void k_first(const float* __restrict__ v,
                                                  const float2* __restrict__ idg,
                                                  float2* __restrict__ dst) {
    int n = blockIdx.y;
    int i0 = blockIdx.x * PXB + threadIdx.x;
    const float* vx = v + (size_t)n * 2 * HW;
    const float* vy = vx + HW;
    float2* o = dst + (size_t)n * HW;
    const float S = 0x1p-32f;

    float dx[4], dy[4];
    float2 g[4];
#pragma unroll
    for (int k = 0; k < 4; ++k) {
        int pi = i0 + k * BLK;
        dx[k] = vx[pi] * S;
        dy[k] = vy[pi] * S;
        g[k] = idg[pi];
    }
#pragma unroll
    for (int k = 0; k < 4; ++k) {
        int pi = i0 + k * BLK;
        float2 s = sampP(vx, vy, g[k].x + dx[k], g[k].y + dy[k], S);
        o[pi] = make_float2(dx[k] + s.x, dy[k] + s.y);
    }
}

// Middle iterations: interleaved -> interleaved, chunk ping-pong.
__global__ __launch_bounds__(BLK, 4) void k_step(const float2* __restrict__ src,
                                                 const float2* __restrict__ idg,
                                                 float2* __restrict__ dst) {
    int n = blockIdx.y;
    int i0 = blockIdx.x * PXB + threadIdx.x;
    const float2* b = src + (size_t)n * HW;
    float2* o = dst + (size_t)n * HW;

    float2 d[4], g[4];
#pragma unroll
    for (int k = 0; k < 4; ++k) {
        int pi = i0 + k * BLK;
        d[k] = b[pi];
        g[k] = idg[pi];
    }
#pragma unroll
    for (int k = 0; k < 4; ++k) {
        int pi = i0 + k * BLK;
        float2 s = samp(b, g[k].x + d[k].x, g[k].y + d[k].y);
        o[pi] = make_float2(d[k].x + s.x, d[k].y + s.y);
    }
}

// Final iteration for one chunk: step + planar output write.
//   out[0:NCHW)      = transformation = idgrid + disp
//   out[NCHW:2*NCHW) = displacement
__global__ __launch_bounds__(BLK, 4) void k_last(const float2* __restrict__ src,
                                                 const float2* __restrict__ idg,
                                                 float* __restrict__ out,
                                                 int nglobBase) {
    int n = blockIdx.y;
    int i0 = blockIdx.x * PXB + threadIdx.x;
    const float2* b = src + (size_t)n * HW;
    size_t base = (size_t)(nglobBase + n) * 2 * HW;

    float2 d[4], g[4];
#pragma unroll
    for (int k = 0; k < 4; ++k) {
        int pi = i0 + k * BLK;
        d[k] = b[pi];
        g[k] = idg[pi];
    }
#pragma unroll
    for (int k = 0; k < 4; ++k) {
        int pi = i0 + k * BLK;
        float2 s = samp(b, g[k].x + d[k].x, g[k].y + d[k].y);
        float nx = d[k].x + s.x;
        float ny = d[k].y + s.y;
        out[base + pi]            = g[k].x + nx;   // transformation ch0
        out[base + HW + pi]       = g[k].y + ny;   // transformation ch1
        out[NCHW + base + pi]     = nx;            // displacement ch0
        out[NCHW + base + HW + pi] = ny;           // displacement ch1
    }
}

extern "C" void kernel_launch(void* const* d_in, const int* in_sizes, int n_in,
                              void* d_out, int out_size) {
    const float* v = (const float*)d_in[0];
    const float2* idg = (const float2*)d_in[1];  // [1,H,W,2] interleaved
    float* out = (float*)d_out;

    float2 *A, *B;
    cudaGetSymbolAddress((void**)&A, g_bufA);
    cudaGetSymbolAddress((void**)&B, g_bufB);

    dim3 threads(BLK);
    dim3 blocks(BLKS_PER_IMG, CH);   // 400 x 8

    for (int c = 0; c < NCHUNK; ++c) {
        const float* vC = v + (size_t)c * CH * 2 * HW;

        // Iteration 0 (reads v planar, scale folded) -> A
        k_first<<<blocks, threads>>>(vC, idg, A);

        // Iterations 1..30 ping-pong within L2-resident scratch
        float2* src = A;
        float2* dst = B;
        for (int it = 1; it <= 30; ++it) {
            k_step<<<blocks, threads>>>(src, idg, dst);
            float2* t = src; src = dst; dst = t;
        }
        // After 30 steps result is back in A (src == A)

        // Iteration 31 fused with planar output write
        k_last<<<blocks, threads>>>(src, idg, out, c * CH);
    }
}

// round 6
// speedup vs baseline: 1.4128x; 1.1258x over previous
#include <cuda_runtime.h>

#define NB 32
#define HH 640
#define WW 640
#define HW (HH * WW)
#define CH 8                    // batches per chunk (scratch = 2*26MB, L2-resident)
#define NCHUNK (NB / CH)
#define NCHW (NB * 2 * HW)

#define BLK 256
#define PXB (BLK * 2)           // 512 consecutive pixels per block
#define BLKS_PER_IMG (HW / PXB) // 800, exact

// Chunk-sized ping-pong scratch, interleaved float2 [CH,H,W,(x,y)].
__device__ float2 g_bufA[CH * HW];
__device__ float2 g_bufB[CH * HW];

// Bilinear sample (border clamp, align_corners=True) from interleaved field
// b[H*W] at normalized coords (tx,ty). EXACT round-3 arithmetic (passing).
__device__ __forceinline__ float2 samp(const float2* __restrict__ b,
                                       float tx, float ty) {
    float px = (tx + 1.0f) * (0.5f * (float)(WW - 1));
    float py = (ty + 1.0f) * (0.5f * (float)(HH - 1));
    px = fminf(fmaxf(px, 0.0f), (float)(WW - 1));
    py = fminf(fmaxf(py, 0.0f), (float)(HH - 1));
    float x0f = floorf(px);
    float y0f = floorf(py);
    int x0 = (int)x0f;
    int y0 = (int)y0f;
    int x1 = min(x0 + 1, WW - 1);
    int y1 = min(y0 + 1, HH - 1);
    float wx = px - x0f;
    float wy = py - y0f;
    float2 v00 = b[y0 * WW + x0];
    float2 v01 = b[y0 * WW + x1];
    float2 v10 = b[y1 * WW + x0];
    float2 v11 = b[y1 * WW + x1];
    float topx = v00.x * (1.0f - wx) + v01.x * wx;
    float topy = v00.y * (1.0f - wx) + v01.y * wx;
    float botx = v10.x * (1.0f - wx) + v11.x * wx;
    float boty = v10.y * (1.0f - wx) + v11.y * wx;
    return make_float2(topx * (1.0f - wy) + botx * wy,
                       topy * (1.0f - wy) + boty * wy);
}

// Planar sampler over v with scale S applied to each tap (exact).
__device__ __forceinline__ float2 sampP(const float* __restrict__ vx,
                                        const float* __restrict__ vy,
                                        float tx, float ty, float S) {
    float px = (tx + 1.0f) * (0.5f * (float)(WW - 1));
    float py = (ty + 1.0f) * (0.5f * (float)(HH - 1));
    px = fminf(fmaxf(px, 0.0f), (float)(WW - 1));
    py = fminf(fmaxf(py, 0.0f), (float)(HH - 1));
    float x0f = floorf(px);
    float y0f = floorf(py);
    int x0 = (int)x0f;
    int y0 = (int)y0f;
    int x1 = min(x0 + 1, WW - 1);
    int y1 = min(y0 + 1, HH - 1);
    float wx = px - x0f;
    float wy = py - y0f;
    float sx, sy;
    {
        float a00 = vx[y0 * WW + x0] * S, a01 = vx[y0 * WW + x1] * S;
        float a10 = vx[y1 * WW + x0] * S, a11 = vx[y1 * WW + x1] * S;
        float top = a00 * (1.0f - wx) + a01 * wx;
        float bot = a10 * (1.0f - wx) + a11 * wx;
        sx = top * (1.0f - wy) + bot * wy;
    }
    {
        float a00 = vy[y0 * WW + x0] * S, a01 = vy[y0 * WW + x1] * S;
        float a10 = vy[y1 * WW + x0] * S, a11 = vy[y1 * WW + x1] * S;
        float top = a00 * (1.0f - wx) + a01 * wx;
        float bot = a10 * (1.0f - wx) + a11 * wx;
        sy = top * (1.0f - wy) + bot * wy;
    }
    return make_float2(sx, sy);
}

// Mapping (all kernels): blockIdx.y = batch-in-chunk, blockIdx.x covers 512
// consecutive pixels; thread t handles the float4 pair at pixel 2t.
// 256-thread blocks + <=32 regs -> 8 blocks/SM = 64 warps (100% occupancy).

// Iteration 0 for one chunk: disp0 = v*2^-32, one step, write interleaved.
__global__ __launch_bounds__(BLK, 8) void k_first(const float* __restrict__ v,
                                                  const float2* __restrict__ idg,
                                                  float2* __restrict__ dst) {
    int n = blockIdx.y;
    int p = blockIdx.x * PXB + threadIdx.x * 2;
    const float* vx = v + (size_t)n * 2 * HW;
    const float* vy = vx + HW;
    const float S = 0x1p-32f;

    float4 g = *reinterpret_cast<const float4*>(idg + p);  // (g0x,g0y,g1x,g1y)

    float d0x = vx[p] * S,     d0y = vy[p] * S;
    float d1x = vx[p + 1] * S, d1y = vy[p + 1] * S;

    float2 s0 = sampP(vx, vy, g.x + d0x, g.y + d0y, S);
    float2 s1 = sampP(vx, vy, g.z + d1x, g.w + d1y, S);

    *reinterpret_cast<float4*>(dst + (size_t)n * HW + p) =
        make_float4(d0x + s0.x, d0y + s0.y, d1x + s1.x, d1y + s1.y);
}

// Middle iterations: interleaved -> interleaved, chunk ping-pong.
__global__ __launch_bounds__(BLK, 8) void k_step(const float2* __restrict__ src,
                                                 const float2* __restrict__ idg,
                                                 float2* __restrict__ dst) {
    int n = blockIdx.y;
    int p = blockIdx.x * PXB + threadIdx.x * 2;
    const float2* b = src + (size_t)n * HW;

    float4 d = *reinterpret_cast<const float4*>(b + p);
    float4 g = *reinterpret_cast<const float4*>(idg + p);

    float2 s0 = samp(b, g.x + d.x, g.y + d.y);
    float2 s1 = samp(b, g.z + d.z, g.w + d.w);

    *reinterpret_cast<float4*>(dst + (size_t)n * HW + p) =
        make_float4(d.x + s0.x, d.y + s0.y, d.z + s1.x, d.w + s1.y);
}

// Final iteration for one chunk: step + planar output write.
//   out[0:NCHW)      = transformation = idgrid + disp
//   out[NCHW:2*NCHW) = displacement
__global__ __launch_bounds__(BLK, 8) void k_last(const float2* __restrict__ src,
                                                 const float2* __restrict__ idg,
                                                 float* __restrict__ out,
                                                 int nglobBase) {
    int n = blockIdx.y;
    int p = blockIdx.x * PXB + threadIdx.x * 2;
    const float2* b = src + (size_t)n * HW;

    float4 d = *reinterpret_cast<const float4*>(b + p);
    float4 g = *reinterpret_cast<const float4*>(idg + p);

    float2 s0 = samp(b, g.x + d.x, g.y + d.y);
    float2 s1 = samp(b, g.z + d.z, g.w + d.w);

    float n0x = d.x + s0.x, n0y = d.y + s0.y;
    float n1x = d.z + s1.x, n1y = d.w + s1.y;

    size_t base = (size_t)(nglobBase + n) * 2 * HW + p;
    // transformation ch0 (x), ch1 (y)
    *reinterpret_cast<float2*>(out + base)      = make_float2(g.x + n0x, g.z + n1x);
    *reinterpret_cast<float2*>(out + base + HW) = make_float2(g.y + n0y, g.w + n1y);
    // displacement ch0, ch1
    *reinterpret_cast<float2*>(out + NCHW + base)      = make_float2(n0x, n1x);
    *reinterpret_cast<float2*>(out + NCHW + base + HW) = make_float2(n0y, n1y);
}

extern "C" void kernel_launch(void* const* d_in, const int* in_sizes, int n_in,
                              void* d_out, int out_size) {
    const float* v = (const float*)d_in[0];
    const float2* idg = (const float2*)d_in[1];  // [1,H,W,2] interleaved
    float* out = (float*)d_out;

    float2 *A, *B;
    cudaGetSymbolAddress((void**)&A, g_bufA);
    cudaGetSymbolAddress((void**)&B, g_bufB);

    dim3 threads(BLK);
    dim3 blocks(BLKS_PER_IMG, CH);   // 800 x 8

    for (int c = 0; c < NCHUNK; ++c) {
        const float* vC = v + (size_t)c * CH * 2 * HW;

        // Iteration 0 (reads v planar, scale folded) -> A
        k_first<<<blocks, threads>>>(vC, idg, A);

        // Iterations 1..30 ping-pong within L2-resident scratch
        float2* src = A;
        float2* dst = B;
        for (int it = 1; it <= 30; ++it) {
            k_step<<<blocks, threads>>>(src, idg, dst);
            float2* t = src; src = dst; dst = t;
        }
        // After 30 steps result is back in A (src == A)

        // Iteration 31 fused with planar output write
        k_last<<<blocks, threads>>>(src, idg, out, c * CH);
    }
}